// round 3
// baseline (speedup 1.0000x reference)
#include <cuda_runtime.h>
#include <math.h>

#define BATCH 2
#define CIN   128
#define TT    5
#define TC    4
#define HH    48
#define WW    48
#define HW    2304
#define HCH   64

// Scratch (device globals -- no allocation allowed)
__device__ float g_q  [BATCH*HW*HCH];        // [b][p][h]
__device__ float g_phi[BATCH*TC*HW*HCH];     // [b][t][p][h]
__device__ float g_g  [BATCH*TC*HW*HCH];     // [b][t][p][h]
__device__ float g_y  [BATCH*HW*HCH];        // flat [b][p*64+k]

// ---------------------------------------------------------------------------
// Kernel 1: projections, single-wave balanced.
// grid (72, 2) = 144 blocks, block 512, dyn smem:
//   wT_theta[128][68], wT_phi[128][68], wT_g[128][68]  (104.4 KB)
//   sx[128 c][32 s]                                     (16 KB)
// Each block: one 32-pixel s-tile, loops all 5 frames with weights resident.
// ---------------------------------------------------------------------------
#define WPAD 68
#define PROJ_SMEM ((3*128*WPAD + 128*32)*4)

__global__ void proj_kernel(const float* __restrict__ x,
                            const float* __restrict__ w_theta,
                            const float* __restrict__ w_phi,
                            const float* __restrict__ w_g)
{
    extern __shared__ float sm[];
    float* wTh = sm;
    float* wPh = sm + 128*WPAD;
    float* wG  = sm + 2*128*WPAD;
    float* sx  = sm + 3*128*WPAD;

    const int s0  = blockIdx.x * 32;
    const int b   = blockIdx.y;
    const int tid = threadIdx.x;

    // stage all three weights transposed [c][h] (pad 68)
    for (int i = tid; i < HCH*CIN; i += 512) {
        int h = i >> 7, c = i & 127;
        wTh[c*WPAD + h] = w_theta[i];
        wPh[c*WPAD + h] = w_phi[i];
        wG [c*WPAD + h] = w_g[i];
    }

    const int lane = tid & 31;          // s within tile
    const int hg   = tid >> 5;          // h group: h = hg*4 + j   (16 groups)

    for (int f = 0; f < TT; f++) {
        __syncthreads();   // previous frame's sx reads done / weights staged
        for (int i = tid; i < 128*32; i += 512) {
            int c = i >> 5, s = i & 31;
            sx[i] = x[((b*CIN + c)*TT + f)*HW + s0 + s];
        }
        __syncthreads();

        if (f == 0) {
            float acc[4] = {};
            #pragma unroll 4
            for (int c = 0; c < 128; c++) {
                float xs = sx[c*32 + lane];
                float4 wa = *(const float4*)(wTh + c*WPAD + hg*4);
                acc[0] = fmaf(wa.x, xs, acc[0]);
                acc[1] = fmaf(wa.y, xs, acc[1]);
                acc[2] = fmaf(wa.z, xs, acc[2]);
                acc[3] = fmaf(wa.w, xs, acc[3]);
            }
            int s = s0 + lane;
            *(float4*)(g_q + (b*HW + s)*HCH + hg*4) =
                make_float4(acc[0], acc[1], acc[2], acc[3]);
        } else {
            float accA[4] = {}, accB[4] = {};
            #pragma unroll 4
            for (int c = 0; c < 128; c++) {
                float xs = sx[c*32 + lane];
                float4 wa = *(const float4*)(wPh + c*WPAD + hg*4);
                float4 wb = *(const float4*)(wG  + c*WPAD + hg*4);
                accA[0] = fmaf(wa.x, xs, accA[0]);
                accA[1] = fmaf(wa.y, xs, accA[1]);
                accA[2] = fmaf(wa.z, xs, accA[2]);
                accA[3] = fmaf(wa.w, xs, accA[3]);
                accB[0] = fmaf(wb.x, xs, accB[0]);
                accB[1] = fmaf(wb.y, xs, accB[1]);
                accB[2] = fmaf(wb.z, xs, accB[2]);
                accB[3] = fmaf(wb.w, xs, accB[3]);
            }
            int t = f - 1;
            int s = s0 + lane;
            size_t base = ((size_t)(b*TC + t)*HW + s)*HCH + hg*4;
            *(float4*)(g_phi + base) = make_float4(accA[0], accA[1], accA[2], accA[3]);
            *(float4*)(g_g   + base) = make_float4(accB[0], accB[1], accB[2], accB[3]);
        }
    }
}

// ---------------------------------------------------------------------------
// Kernel 2: attention with scrambled-V gather.
// grid (6,12,2), block 1024 (32 warps = 4x8 pixel tile).
// Smem layout (floats):
//   [0, 36096)            g halos, channel-major [t][64][141]
//   [36096, 48640)        UNION: phi [140][68] (pass1) / offT int[12544] (pass2)
//   [48640, 55040)        satt [32 warps][200]
//   [55040, 55180)        sgp  int[140] gathered pixel offsets (*64)
// total 55180 floats = 220720 B
// ---------------------------------------------------------------------------
#define SGM_F   0
#define UNI_F   36096
#define SATT_F  48640
#define SGP_F   55040
#define SMEM_F  55180

__global__ void attn_kernel()
{
    extern __shared__ float sm[];
    float* sgm  = sm + SGM_F;
    float* sphi = sm + UNI_F;
    float* satt = sm + SATT_F;
    int*   sgp  = (int*)(sm + SGP_F);

    const int b    = blockIdx.z;
    const int tid  = threadIdx.x;
    const int lane = tid & 31, warp = tid >> 5;
    const int ly = warp >> 3, lx = warp & 7;
    const int py = blockIdx.y*4 + ly;
    const int px = blockIdx.x*8 + lx;
    const int p  = py*WW + px;
    const int warpPos = ly*14 + lx;

    if (tid < 140) {
        int hy = tid / 14, hx = tid - hy*14;
        int gy = min(max((int)blockIdx.y*4 + hy - 3, 0), HH-1);
        int gx = min(max((int)blockIdx.x*8 + hx - 3, 0), WW-1);
        sgp[tid] = (gy*WW + gx)*HCH;
    }
    __syncthreads();

    // ---- load all 4 frames of g halos, channel-major [t][h][141] ----
    const float* gBase = g_g + (size_t)b*TC*HW*HCH;
    for (int i = tid; i < TC*140*64; i += 1024) {
        int h  = i & 63;
        int pr = i >> 6;
        int pos = pr % 140;
        int t   = pr / 140;
        sgm[(t*64 + h)*141 + pos] = gBase[t*HW*HCH + sgp[pos] + h];
    }

    // ---- q for this pixel ----
    const float* qb = g_q + (b*HW + p)*HCH;
    const int c   = lane & 7;    // channel chunk within key group
    const int sub = lane >> 3;   // key within group of 4
    float4 qv0 = *(const float4*)(qb + c*4);
    float4 qv1 = *(const float4*)(qb + c*4 + 32);
    float  q0r = qb[lane], q1r = qb[lane + 32];

    // ---- pass 1: scores (phi, unscrambled) ----
    const float* pBase = g_phi + (size_t)b*TC*HW*HCH;
    for (int t = 0; t < TC; t++) {
        __syncthreads();   // previous frame's phi reads done
        for (int i = tid; i < 140*16; i += 1024) {
            int c4 = i & 15, pos = i >> 4;
            *(float4*)(sphi + pos*68 + c4*4) =
                *(const float4*)(pBase + t*HW*HCH + sgp[pos] + c4*4);
        }
        __syncthreads();

        #pragma unroll
        for (int g2 = 0; g2 < 12; g2++) {
            int q  = g2*4 + sub;
            int dy = q / 7, dx = q - dy*7;
            int pos = warpPos + dy*14 + dx;
            const float4* pr4 = (const float4*)(sphi + pos*68);
            float4 p0 = pr4[c];
            float4 p1 = pr4[8 + c];
            float s = qv0.x*p0.x + qv0.y*p0.y + qv0.z*p0.z + qv0.w*p0.w
                    + qv1.x*p1.x + qv1.y*p1.y + qv1.z*p1.z + qv1.w*p1.w;
            s += __shfl_xor_sync(0xffffffffu, s, 4);
            s += __shfl_xor_sync(0xffffffffu, s, 2);
            s += __shfl_xor_sync(0xffffffffu, s, 1);
            if (c == 0) satt[warp*200 + t*49 + q] = s * 8.0f;
        }
        // leftover key q=48 (dy=6,dx=6)
        {
            int pos = warpPos + 90;
            float s = q0r*sphi[pos*68 + lane] + q1r*sphi[pos*68 + lane + 32];
            s += __shfl_xor_sync(0xffffffffu, s, 16);
            s += __shfl_xor_sync(0xffffffffu, s, 8);
            s += __shfl_xor_sync(0xffffffffu, s, 4);
            s += __shfl_xor_sync(0xffffffffu, s, 2);
            s += __shfl_xor_sync(0xffffffffu, s, 1);
            if (lane == 0) satt[warp*200 + t*49 + 48] = s * 8.0f;
        }
    }
    __syncthreads();   // all pass-1 phi reads done; union region free

    // ---- compute scramble table offT directly into smem (aliases phi) ----
    // i = k*64+j -> element (h,t,dy,dx) of per-pixel flat [64][4][7][7]
    {
        int* dst = (int*)sphi;
        for (int i = tid; i < 12544; i += 1024) {
            int h  = i / 196;
            int r  = i - h*196;
            int t  = r / 49;
            int q  = r - t*49;
            int dy = q / 7;
            int dx = q - dy*7;
            dst[i] = (t*64 + h)*141 + dy*14 + dx;
        }
    }

    // ---- per-warp softmax over 196 raw scores (deferred normalization) ----
    float sv[7];
    float m = -1e30f;
    #pragma unroll
    for (int g2 = 0; g2 < 7; g2++) {
        int k = lane + 32*g2;
        sv[g2] = (k < 196) ? satt[warp*200 + k] : -1e30f;
        m = fmaxf(m, sv[g2]);
    }
    m = fmaxf(m, __shfl_xor_sync(0xffffffffu, m, 16));
    m = fmaxf(m, __shfl_xor_sync(0xffffffffu, m, 8));
    m = fmaxf(m, __shfl_xor_sync(0xffffffffu, m, 4));
    m = fmaxf(m, __shfl_xor_sync(0xffffffffu, m, 2));
    m = fmaxf(m, __shfl_xor_sync(0xffffffffu, m, 1));
    float tot = 0.f;
    #pragma unroll
    for (int g2 = 0; g2 < 7; g2++) {
        int k = lane + 32*g2;
        if (k < 196) {
            float e = __expf(sv[g2] - m);
            satt[warp*200 + k] = e;
            tot += e;
        }
    }
    tot += __shfl_xor_sync(0xffffffffu, tot, 16);
    tot += __shfl_xor_sync(0xffffffffu, tot, 8);
    tot += __shfl_xor_sync(0xffffffffu, tot, 4);
    tot += __shfl_xor_sync(0xffffffffu, tot, 2);
    tot += __shfl_xor_sync(0xffffffffu, tot, 1);
    float inv = 1.0f / tot;

    __syncthreads();   // offT ready

    // ---- pass 2: scrambled-V accumulation ----
    const int* soff = (const int*)sphi;
    float acc0 = 0.f, acc1 = 0.f;
    for (int k = 0; k < 196; k += 4) {
        float4 w4 = *(const float4*)(satt + warp*200 + k);
        float wv[4] = {w4.x, w4.y, w4.z, w4.w};
        #pragma unroll
        for (int u = 0; u < 4; u++) {
            int base = (k + u)*64 + lane;
            int o0 = soff[base];
            int o1 = soff[base + 32];
            acc0 = fmaf(wv[u], sgm[o0 + warpPos], acc0);
            acc1 = fmaf(wv[u], sgm[o1 + warpPos], acc1);
        }
    }
    float* yb = g_y + (b*HW + p)*HCH;
    yb[lane]      = acc0 * inv;
    yb[lane + 32] = acc1 * inv;
}

// ---------------------------------------------------------------------------
// Kernel 3: output projection + residual (handles the y-reshape scramble).
// out[b,c,s] = x[b,c,0,s] + sum_h' w_out[c,h'] * y_flat[b][h'*2304 + s]
// grid (36,2,2), block 512, microtile 2c x 4s.
// ---------------------------------------------------------------------------
__global__ void out_kernel(const float* __restrict__ x,
                           const float* __restrict__ w_out,
                           float* __restrict__ out)
{
    __shared__ float sy [64*64];   // [h'][s]
    __shared__ float swt[64*68];   // [h'][c]
    const int s0  = blockIdx.x * 64;
    const int c0  = blockIdx.y * 64;
    const int b   = blockIdx.z;
    const int tid = threadIdx.x;
    const float* yb = g_y + b*HW*HCH;
    for (int i = tid; i < 4096; i += 512) {
        int hh = i >> 6, s = i & 63;
        sy[i] = yb[hh*HW + s0 + s];
        int cc = i >> 6, h2 = i & 63;
        swt[h2*68 + cc] = w_out[(c0 + cc)*HCH + h2];
    }
    __syncthreads();
    const int sg2 = tid & 15;   // s = sg2*4 + i
    const int cg  = tid >> 4;   // c = cg*2 + j   (32 groups)
    float acc[2][4] = {};
    #pragma unroll 4
    for (int hh = 0; hh < 64; hh++) {
        float4 yv = *(const float4*)(sy + hh*64 + sg2*4);
        float2 wv = *(const float2*)(swt + hh*68 + cg*2);
        float ys[4] = {yv.x, yv.y, yv.z, yv.w};
        float ws[2] = {wv.x, wv.y};
        #pragma unroll
        for (int j = 0; j < 2; j++)
            #pragma unroll
            for (int i = 0; i < 4; i++)
                acc[j][i] = fmaf(ws[j], ys[i], acc[j][i]);
    }
    #pragma unroll
    for (int j = 0; j < 2; j++) {
        int cc = c0 + cg*2 + j;
        float4 xv = *(const float4*)(x + (b*CIN + cc)*TT*HW + s0 + sg2*4);
        float4 o  = make_float4(acc[j][0]+xv.x, acc[j][1]+xv.y,
                                acc[j][2]+xv.z, acc[j][3]+xv.w);
        *(float4*)(out + (b*CIN + cc)*HW + s0 + sg2*4) = o;
    }
}

extern "C" void kernel_launch(void* const* d_in, const int* in_sizes, int n_in,
                              void* d_out, int out_size)
{
    const float* x  = (const float*)d_in[0];
    const float* wt = (const float*)d_in[1];
    const float* wp = (const float*)d_in[2];
    const float* wg = (const float*)d_in[3];
    const float* wo = (const float*)d_in[4];
    float* out = (float*)d_out;

    cudaFuncSetAttribute(proj_kernel, cudaFuncAttributeMaxDynamicSharedMemorySize, PROJ_SMEM);
    cudaFuncSetAttribute(attn_kernel, cudaFuncAttributeMaxDynamicSharedMemorySize, SMEM_F*4);

    proj_kernel<<<dim3(72, 2), 512, PROJ_SMEM>>>(x, wt, wp, wg);
    attn_kernel<<<dim3(6, 12, 2), 1024, SMEM_F*4>>>();
    out_kernel<<<dim3(36, 2, 2), 512>>>(x, wo, out);
}

// round 5
// speedup vs baseline: 1.2152x; 1.2152x over previous
#include <cuda_runtime.h>
#include <cuda_bf16.h>
#include <math.h>

#define BATCH 2
#define CIN   128
#define TT    5
#define TC    4
#define HH    48
#define WW    48
#define HW    2304
#define HCH   64

// Scratch (device globals -- no allocation allowed)
__device__ float          g_q  [BATCH*HW*HCH];      // [b][p][h] fp32
__device__ float          g_phi[BATCH*TC*HW*HCH];   // [b][t][p][h] fp32
__device__ __nv_bfloat16  g_gb [BATCH*TC*HW*HCH];   // [b][t][p][h] bf16
__device__ float          g_y  [BATCH*HW*HCH];      // flat [b][p*64+j]

// ---- packed fp32x2 helpers (sm_100+) ----
__device__ __forceinline__ unsigned long long pack2(float x, float y) {
    unsigned long long r;
    asm("mov.b64 %0, {%1, %2};" : "=l"(r) : "f"(x), "f"(y));
    return r;
}
__device__ __forceinline__ void unpack2(unsigned long long v, float& x, float& y) {
    asm("mov.b64 {%0, %1}, %2;" : "=f"(x), "=f"(y) : "l"(v));
}
__device__ __forceinline__ unsigned long long ffma2(unsigned long long a,
                                                    unsigned long long b,
                                                    unsigned long long c) {
    unsigned long long d;
    asm("fma.rn.f32x2 %0, %1, %2, %3;" : "=l"(d) : "l"(a), "l"(b), "l"(c));
    return d;
}

// ---------------------------------------------------------------------------
// Kernel 1: projections, register-tiled 4h x 4s, packed f32x2 FMA.
// grid (36 s-tiles, 5 frames, 2 batch) = 360 blocks, 256 threads.
// smem: wA[128][68], wB[128][68] fp32 transposed; sx[128 c][64 s].
// ---------------------------------------------------------------------------
#define WPAD 68
#define PROJ_SMEM ((2*128*WPAD + 128*64)*4)

__global__ void proj_kernel(const float* __restrict__ x,
                            const float* __restrict__ w_theta,
                            const float* __restrict__ w_phi,
                            const float* __restrict__ w_g)
{
    extern __shared__ float sm[];
    float* wA = sm;                  // theta (f=0) or phi (f>0)
    float* wB = sm + 128*WPAD;       // g (f>0 only)
    float* sx = sm + 2*128*WPAD;     // [c][64]

    const int s0  = blockIdx.x * 64;
    const int f   = blockIdx.y;
    const int b   = blockIdx.z;
    const int tid = threadIdx.x;

    const float* wsrcA = (f == 0) ? w_theta : w_phi;
    for (int i = tid; i < HCH*CIN; i += 256) {
        int h = i >> 7, c = i & 127;
        wA[c*WPAD + h] = wsrcA[i];
    }
    if (f > 0) {
        for (int i = tid; i < HCH*CIN; i += 256) {
            int h = i >> 7, c = i & 127;
            wB[c*WPAD + h] = w_g[i];
        }
    }
    for (int i = tid; i < 128*64; i += 256) {
        int c = i >> 6, s = i & 63;
        sx[i] = x[((b*CIN + c)*TT + f)*HW + s0 + s];
    }
    __syncthreads();

    const int sg = tid & 15;    // s quad: s = s0 + sg*4 + i
    const int hg = tid >> 4;    // h quad: h = hg*4 + (pair*2 + half)

    if (f == 0) {
        unsigned long long acc[4][2] = {};   // [s i][h pair]
        #pragma unroll 4
        for (int c = 0; c < 128; c++) {
            float4 xs = *(const float4*)(sx + c*64 + sg*4);
            ulonglong2 wa = *(const ulonglong2*)(wA + c*WPAD + hg*4);
            unsigned long long xp[4] = {pack2(xs.x, xs.x), pack2(xs.y, xs.y),
                                        pack2(xs.z, xs.z), pack2(xs.w, xs.w)};
            #pragma unroll
            for (int i = 0; i < 4; i++) {
                acc[i][0] = ffma2(wa.x, xp[i], acc[i][0]);
                acc[i][1] = ffma2(wa.y, xp[i], acc[i][1]);
            }
        }
        #pragma unroll
        for (int i = 0; i < 4; i++) {
            int s = s0 + sg*4 + i;
            *(ulonglong2*)(g_q + ((size_t)b*HW + s)*HCH + hg*4) =
                make_ulonglong2(acc[i][0], acc[i][1]);
        }
    } else {
        unsigned long long accA[4][2] = {};  // phi
        unsigned long long accB[4][2] = {};  // g
        #pragma unroll 2
        for (int c = 0; c < 128; c++) {
            float4 xs = *(const float4*)(sx + c*64 + sg*4);
            ulonglong2 wa = *(const ulonglong2*)(wA + c*WPAD + hg*4);
            ulonglong2 wb = *(const ulonglong2*)(wB + c*WPAD + hg*4);
            unsigned long long xp[4] = {pack2(xs.x, xs.x), pack2(xs.y, xs.y),
                                        pack2(xs.z, xs.z), pack2(xs.w, xs.w)};
            #pragma unroll
            for (int i = 0; i < 4; i++) {
                accA[i][0] = ffma2(wa.x, xp[i], accA[i][0]);
                accA[i][1] = ffma2(wa.y, xp[i], accA[i][1]);
                accB[i][0] = ffma2(wb.x, xp[i], accB[i][0]);
                accB[i][1] = ffma2(wb.y, xp[i], accB[i][1]);
            }
        }
        const int t = f - 1;
        #pragma unroll
        for (int i = 0; i < 4; i++) {
            int s = s0 + sg*4 + i;
            size_t base = ((size_t)(b*TC + t)*HW + s)*HCH + hg*4;
            *(ulonglong2*)(g_phi + base) = make_ulonglong2(accA[i][0], accA[i][1]);
            float b0, b1, b2, b3;
            unpack2(accB[i][0], b0, b1);
            unpack2(accB[i][1], b2, b3);
            __nv_bfloat162 p0 = __floats2bfloat162_rn(b0, b1);
            __nv_bfloat162 p1 = __floats2bfloat162_rn(b2, b3);
            uint2 pk = make_uint2(*(unsigned int*)&p0, *(unsigned int*)&p1);
            *(uint2*)(&g_gb[base]) = pk;
        }
    }
}

// ---------------------------------------------------------------------------
// Kernel 2: attention.  grid (6,12,2), block 1024 (32 warps = 4x8 pixel tile).
// Smem layout (bytes):
//   [0, 72192)          g halos bf16, channel-major [t][64][141]
//   [72192, 110272)     UNION: phi fp32 [140][68] (pass1) / offT ushort[12544]
//   [110272, 135872)    satt fp32 [32 warps][200]
//   [135872, 136432)    sgp int[140]
// ---------------------------------------------------------------------------
#define SGM_B   0
#define UNI_B   72192
#define SATT_B  110272
#define SGP_B   135872
#define SMEM_B  136432

__global__ void attn_kernel()
{
    extern __shared__ char smc[];
    __nv_bfloat16* sgm16 = (__nv_bfloat16*)(smc + SGM_B);
    float*         sphi  = (float*)(smc + UNI_B);
    float*         satt  = (float*)(smc + SATT_B);
    int*           sgp   = (int*)(smc + SGP_B);

    const int b    = blockIdx.z;
    const int tid  = threadIdx.x;
    const int lane = tid & 31, warp = tid >> 5;
    const int ly = warp >> 3, lx = warp & 7;
    const int py = blockIdx.y*4 + ly;
    const int px = blockIdx.x*8 + lx;
    const int p  = py*WW + px;
    const int warpPos = ly*14 + lx;

    if (tid < 140) {
        int hy = tid / 14, hx = tid - hy*14;
        int gy = min(max((int)blockIdx.y*4 + hy - 3, 0), HH-1);
        int gx = min(max((int)blockIdx.x*8 + hx - 3, 0), WW-1);
        sgp[tid] = (gy*WW + gx)*HCH;
    }
    __syncthreads();

    // ---- stage all 4 frames of g halos, bf16 channel-major [t][h][141] ----
    const __nv_bfloat16* gBase = g_gb + (size_t)b*TC*HW*HCH;
    for (int i = tid; i < 560*32; i += 1024) {
        int h2  = i & 31;          // channel pair 2h2, 2h2+1
        int pr  = i >> 5;
        int pos = pr % 140;
        int t   = pr / 140;
        unsigned int v = *(const unsigned int*)(gBase + (size_t)t*HW*HCH + sgp[pos] + 2*h2);
        __nv_bfloat162 bv = *(__nv_bfloat162*)&v;
        sgm16[(t*64 + 2*h2    )*141 + pos] = bv.x;
        sgm16[(t*64 + 2*h2 + 1)*141 + pos] = bv.y;
    }

    // ---- q for this pixel ----
    const float* qb = g_q + ((size_t)b*HW + p)*HCH;
    const int c   = lane & 7;    // channel chunk within key group
    const int sub = lane >> 3;   // key within group of 4
    float4 qv0 = *(const float4*)(qb + c*4);
    float4 qv1 = *(const float4*)(qb + c*4 + 32);
    float  q0r = qb[lane], q1r = qb[lane + 32];

    // ---- pass 1: scores (phi fp32, unscrambled) ----
    const float* pBase = g_phi + (size_t)b*TC*HW*HCH;
    for (int t = 0; t < TC; t++) {
        __syncthreads();
        for (int i = tid; i < 140*16; i += 1024) {
            int c4 = i & 15, pos = i >> 4;
            *(float4*)(sphi + pos*68 + c4*4) =
                *(const float4*)(pBase + (size_t)t*HW*HCH + sgp[pos] + c4*4);
        }
        __syncthreads();

        #pragma unroll
        for (int g2 = 0; g2 < 12; g2++) {
            int q  = g2*4 + sub;
            int dy = q / 7, dx = q - dy*7;
            int pos = warpPos + dy*14 + dx;
            const float4* pr4 = (const float4*)(sphi + pos*68);
            float4 p0 = pr4[c];
            float4 p1 = pr4[8 + c];
            float s = qv0.x*p0.x + qv0.y*p0.y + qv0.z*p0.z + qv0.w*p0.w
                    + qv1.x*p1.x + qv1.y*p1.y + qv1.z*p1.z + qv1.w*p1.w;
            s += __shfl_xor_sync(0xffffffffu, s, 4);
            s += __shfl_xor_sync(0xffffffffu, s, 2);
            s += __shfl_xor_sync(0xffffffffu, s, 1);
            if (c == 0) satt[warp*200 + t*49 + q] = s * 8.0f;
        }
        {   // leftover key q=48
            int pos = warpPos + 90;
            float s = q0r*sphi[pos*68 + lane] + q1r*sphi[pos*68 + lane + 32];
            s += __shfl_xor_sync(0xffffffffu, s, 16);
            s += __shfl_xor_sync(0xffffffffu, s, 8);
            s += __shfl_xor_sync(0xffffffffu, s, 4);
            s += __shfl_xor_sync(0xffffffffu, s, 2);
            s += __shfl_xor_sync(0xffffffffu, s, 1);
            if (lane == 0) satt[warp*200 + t*49 + 48] = s * 8.0f;
        }
    }
    __syncthreads();   // pass-1 phi reads done; union region free

    // ---- compute scramble table (ushort) into union region ----
    {
        unsigned short* dst = (unsigned short*)(smc + UNI_B);
        for (int i = tid; i < 12544; i += 1024) {
            int h  = i / 196;
            int r  = i - h*196;
            int t  = r / 49;
            int q  = r - t*49;
            int dy = q / 7;
            int dx = q - dy*7;
            dst[i] = (unsigned short)((t*64 + h)*141 + dy*14 + dx);
        }
    }

    // ---- per-warp softmax (deferred normalization) ----
    float sv[7];
    float m = -1e30f;
    #pragma unroll
    for (int g2 = 0; g2 < 7; g2++) {
        int k = lane + 32*g2;
        sv[g2] = (k < 196) ? satt[warp*200 + k] : -1e30f;
        m = fmaxf(m, sv[g2]);
    }
    m = fmaxf(m, __shfl_xor_sync(0xffffffffu, m, 16));
    m = fmaxf(m, __shfl_xor_sync(0xffffffffu, m, 8));
    m = fmaxf(m, __shfl_xor_sync(0xffffffffu, m, 4));
    m = fmaxf(m, __shfl_xor_sync(0xffffffffu, m, 2));
    m = fmaxf(m, __shfl_xor_sync(0xffffffffu, m, 1));
    float tot = 0.f;
    #pragma unroll
    for (int g2 = 0; g2 < 7; g2++) {
        int k = lane + 32*g2;
        if (k < 196) {
            float e = __expf(sv[g2] - m);
            satt[warp*200 + k] = e;
            tot += e;
        }
    }
    tot += __shfl_xor_sync(0xffffffffu, tot, 16);
    tot += __shfl_xor_sync(0xffffffffu, tot, 8);
    tot += __shfl_xor_sync(0xffffffffu, tot, 4);
    tot += __shfl_xor_sync(0xffffffffu, tot, 2);
    tot += __shfl_xor_sync(0xffffffffu, tot, 1);
    float inv = 1.0f / tot;

    __syncthreads();   // offT ready

    // ---- pass 2: scrambled-V accumulation (channels 2*lane, 2*lane+1) ----
    const ushort2* soff2 = (const ushort2*)(smc + UNI_B);
    float acc0 = 0.f, acc1 = 0.f;
    for (int k = 0; k < 196; k += 4) {
        float4 w4 = *(const float4*)(satt + warp*200 + k);
        float wv[4] = {w4.x, w4.y, w4.z, w4.w};
        #pragma unroll
        for (int u = 0; u < 4; u++) {
            ushort2 o = soff2[(k + u)*32 + lane];
            acc0 = fmaf(wv[u], __bfloat162float(sgm16[o.x + warpPos]), acc0);
            acc1 = fmaf(wv[u], __bfloat162float(sgm16[o.y + warpPos]), acc1);
        }
    }
    float* yb = g_y + ((size_t)b*HW + p)*HCH;
    *(float2*)(yb + 2*lane) = make_float2(acc0*inv, acc1*inv);
}

// ---------------------------------------------------------------------------
// Kernel 3: output projection + residual (handles the y-reshape scramble).
// out[b,c,s] = x[b,c,0,s] + sum_h' w_out[c,h'] * y_flat[b][h'*2304 + s]
// grid (36,2,2), block 512, microtile 2c x 4s.
// ---------------------------------------------------------------------------
__global__ void out_kernel(const float* __restrict__ x,
                           const float* __restrict__ w_out,
                           float* __restrict__ out)
{
    __shared__ float sy [64*64];   // [h'][s]
    __shared__ float swt[64*68];   // [h'][c]
    const int s0  = blockIdx.x * 64;
    const int c0  = blockIdx.y * 64;
    const int b   = blockIdx.z;
    const int tid = threadIdx.x;
    const float* yb = g_y + (size_t)b*HW*HCH;
    for (int i = tid; i < 4096; i += 512) {
        int hh = i >> 6, s = i & 63;
        sy[i] = yb[hh*HW + s0 + s];
        int cc = i >> 6, h2 = i & 63;
        swt[h2*68 + cc] = w_out[(c0 + cc)*HCH + h2];
    }
    __syncthreads();
    const int sg2 = tid & 15;   // s = sg2*4 + i
    const int cg  = tid >> 4;   // c = cg*2 + j
    float acc[2][4] = {};
    #pragma unroll 4
    for (int hh = 0; hh < 64; hh++) {
        float4 yv = *(const float4*)(sy + hh*64 + sg2*4);
        float2 wv = *(const float2*)(swt + hh*68 + cg*2);
        float ys[4] = {yv.x, yv.y, yv.z, yv.w};
        float ws[2] = {wv.x, wv.y};
        #pragma unroll
        for (int j = 0; j < 2; j++)
            #pragma unroll
            for (int i = 0; i < 4; i++)
                acc[j][i] = fmaf(ws[j], ys[i], acc[j][i]);
    }
    #pragma unroll
    for (int j = 0; j < 2; j++) {
        int cc = c0 + cg*2 + j;
        float4 xv = *(const float4*)(x + ((size_t)(b*CIN + cc)*TT)*HW + s0 + sg2*4);
        float4 o  = make_float4(acc[j][0]+xv.x, acc[j][1]+xv.y,
                                acc[j][2]+xv.z, acc[j][3]+xv.w);
        *(float4*)(out + ((size_t)(b*CIN + cc))*HW + s0 + sg2*4) = o;
    }
}

extern "C" void kernel_launch(void* const* d_in, const int* in_sizes, int n_in,
                              void* d_out, int out_size)
{
    const float* x  = (const float*)d_in[0];
    const float* wt = (const float*)d_in[1];
    const float* wp = (const float*)d_in[2];
    const float* wg = (const float*)d_in[3];
    const float* wo = (const float*)d_in[4];
    float* out = (float*)d_out;

    cudaFuncSetAttribute(proj_kernel, cudaFuncAttributeMaxDynamicSharedMemorySize, PROJ_SMEM);
    cudaFuncSetAttribute(attn_kernel, cudaFuncAttributeMaxDynamicSharedMemorySize, SMEM_B);

    proj_kernel<<<dim3(36, 5, 2), 256, PROJ_SMEM>>>(x, wt, wp, wg);
    attn_kernel<<<dim3(6, 12, 2), 1024, SMEM_B>>>();
    out_kernel<<<dim3(36, 2, 2), 512>>>(x, wo, out);
}

// round 7
// speedup vs baseline: 1.6149x; 1.3289x over previous
#include <cuda_runtime.h>
#include <cuda_bf16.h>
#include <math.h>
#include <cstdint>

#define BATCH 2
#define CIN   128
#define TT    5
#define TC    4
#define HH    48
#define WW    48
#define HW    2304
#define HCH   64

// Scratch (device globals -- no allocation allowed)
__device__ float          g_q  [BATCH*HW*HCH];      // [b][p][h] fp32
__device__ float          g_phi[BATCH*TC*HW*HCH];   // [b][t][p][h] fp32
__device__ __nv_bfloat16  g_gb [BATCH*TC*HW*HCH];   // [b][t][p][h] bf16
__device__ float          g_y  [BATCH*HW*HCH];      // flat [b][p*64+j]

// ---------------------------------------------------------------------------
// Kernel 1: projections via warp-level bf16 HMMA (mma.sync m16n8k16).
// grid (36, 5, 2), block 256 (8 warps = 4m x 2n).
// D[128 out][64 px] = A[128,128] x B[128,64]:
//   A rows 0-63  = w_theta (f=0) / w_phi (f>0)
//   A rows 64-127= dup (f=0, skipped) / w_g (f>0)
// smem: W_sm uint32[128][68]  (bf16 pair along k), X_sm uint32[64][72].
// ---------------------------------------------------------------------------
#define WSTRIDE 68
#define XSTRIDE 72
#define PROJ_SMEM ((128*WSTRIDE + 64*XSTRIDE)*4)

__global__ void __launch_bounds__(256)
proj_kernel(const float* __restrict__ x,
            const float* __restrict__ w_theta,
            const float* __restrict__ w_phi,
            const float* __restrict__ w_g)
{
    extern __shared__ uint32_t smw[];              // W_sm [128][WSTRIDE]
    uint32_t* smx = smw + 128*WSTRIDE;             // X_sm [64][XSTRIDE]

    const int s0  = blockIdx.x * 64;
    const int f   = blockIdx.y;
    const int b   = blockIdx.z;
    const int tid = threadIdx.x;

    // ---- stage W: bf16 pairs (k, k+1) at [m][k2] ----
    const float* wsrcA = (f == 0) ? w_theta : w_phi;
    const float* wsrcB = (f == 0) ? w_theta : w_g;
    for (int i = tid; i < 8192; i += 256) {
        int m = i >> 6, k2 = i & 63;
        const float* row = (m < 64) ? (wsrcA + m*CIN) : (wsrcB + (m - 64)*CIN);
        float2 wv = *(const float2*)(row + 2*k2);
        __nv_bfloat162 bp = __floats2bfloat162_rn(wv.x, wv.y);
        smw[m*WSTRIDE + k2] = *(uint32_t*)&bp;
    }
    // ---- stage X: bf16 pairs (c, c+1) at [k2][n] ----
    const float* xb = x + ((size_t)(b*CIN))*TT*HW + (size_t)f*HW + s0;
    for (int i = tid; i < 4096; i += 256) {
        int k2 = i >> 6, n = i & 63;
        float x0 = xb[(size_t)(2*k2    )*(TT*HW) + n];
        float x1 = xb[(size_t)(2*k2 + 1)*(TT*HW) + n];
        __nv_bfloat162 bp = __floats2bfloat162_rn(x0, x1);
        smx[k2*XSTRIDE + n] = *(uint32_t*)&bp;
    }
    __syncthreads();

    const int warp = tid >> 5, lane = tid & 31;
    const int l4 = lane >> 2, lm4 = lane & 3;
    const int m0  = (warp & 3) * 32;
    const int n0w = (warp >> 2) * 32;

    if (f == 0 && m0 >= 64) return;   // duplicate theta rows; no syncthreads after

    float acc[2][4][4] = {};          // [mi][ni][c0..c3]
    #pragma unroll
    for (int k8 = 0; k8 < 8; k8++) {
        uint32_t a[2][4];
        #pragma unroll
        for (int mi = 0; mi < 2; mi++) {
            int r0 = m0 + mi*16 + l4;
            int cA = k8*8 + lm4;
            a[mi][0] = smw[r0*WSTRIDE + cA];
            a[mi][1] = smw[(r0 + 8)*WSTRIDE + cA];
            a[mi][2] = smw[r0*WSTRIDE + cA + 4];
            a[mi][3] = smw[(r0 + 8)*WSTRIDE + cA + 4];
        }
        #pragma unroll
        for (int ni = 0; ni < 4; ni++) {
            int ncol = n0w + ni*8 + l4;
            uint32_t b0 = smx[(k8*8 + lm4    )*XSTRIDE + ncol];
            uint32_t b1 = smx[(k8*8 + lm4 + 4)*XSTRIDE + ncol];
            #pragma unroll
            for (int mi = 0; mi < 2; mi++) {
                asm volatile(
                    "mma.sync.aligned.m16n8k16.row.col.f32.bf16.bf16.f32 "
                    "{%0,%1,%2,%3}, {%4,%5,%6,%7}, {%8,%9}, {%0,%1,%2,%3};\n"
                    : "+f"(acc[mi][ni][0]), "+f"(acc[mi][ni][1]),
                      "+f"(acc[mi][ni][2]), "+f"(acc[mi][ni][3])
                    : "r"(a[mi][0]), "r"(a[mi][1]), "r"(a[mi][2]), "r"(a[mi][3]),
                      "r"(b0), "r"(b1));
            }
        }
    }

    // ---- epilogue: c0:(r, s) c1:(r, s+1) c2:(r+8, s) c3:(r+8, s+1) ----
    const int t = f - 1;
    #pragma unroll
    for (int mi = 0; mi < 2; mi++) {
        int r = m0 + mi*16 + l4;
        #pragma unroll
        for (int ni = 0; ni < 4; ni++) {
            int s = s0 + n0w + ni*8 + lm4*2;
            if (f == 0) {
                float* q = g_q + (size_t)b*HW*HCH;
                q[(size_t)(s    )*HCH + r]     = acc[mi][ni][0];
                q[(size_t)(s + 1)*HCH + r]     = acc[mi][ni][1];
                q[(size_t)(s    )*HCH + r + 8] = acc[mi][ni][2];
                q[(size_t)(s + 1)*HCH + r + 8] = acc[mi][ni][3];
            } else if (m0 < 64) {
                float* ph = g_phi + ((size_t)(b*TC + t)*HW)*HCH;
                ph[(size_t)(s    )*HCH + r]     = acc[mi][ni][0];
                ph[(size_t)(s + 1)*HCH + r]     = acc[mi][ni][1];
                ph[(size_t)(s    )*HCH + r + 8] = acc[mi][ni][2];
                ph[(size_t)(s + 1)*HCH + r + 8] = acc[mi][ni][3];
            } else {
                __nv_bfloat16* gg = g_gb + ((size_t)(b*TC + t)*HW)*HCH;
                int h = r - 64;
                gg[(size_t)(s    )*HCH + h]     = __float2bfloat16(acc[mi][ni][0]);
                gg[(size_t)(s + 1)*HCH + h]     = __float2bfloat16(acc[mi][ni][1]);
                gg[(size_t)(s    )*HCH + h + 8] = __float2bfloat16(acc[mi][ni][2]);
                gg[(size_t)(s + 1)*HCH + h + 8] = __float2bfloat16(acc[mi][ni][3]);
            }
        }
    }
}

// ---------------------------------------------------------------------------
// Kernel 2: attention.  grid (6,12,2), block 1024 (32 warps = 4x8 pixel tile).
// Smem layout (bytes):
//   [0, 72192)          g halos bf16, channel-major [t][64][141]
//   [72192, 110272)     UNION: phi fp32 [140][68] (pass1) / offT ushort[12544]
//   [110272, 135872)    satt fp32 [32 warps][200]
//   [135872, 136432)    sgp int[140]
// ---------------------------------------------------------------------------
#define SGM_B   0
#define UNI_B   72192
#define SATT_B  110272
#define SGP_B   135872
#define SMEM_B  136432

__global__ void attn_kernel()
{
    extern __shared__ char smc[];
    __nv_bfloat16* sgm16 = (__nv_bfloat16*)(smc + SGM_B);
    float*         sphi  = (float*)(smc + UNI_B);
    float*         satt  = (float*)(smc + SATT_B);
    int*           sgp   = (int*)(smc + SGP_B);

    const int b    = blockIdx.z;
    const int tid  = threadIdx.x;
    const int lane = tid & 31, warp = tid >> 5;
    const int ly = warp >> 3, lx = warp & 7;
    const int py = blockIdx.y*4 + ly;
    const int px = blockIdx.x*8 + lx;
    const int p  = py*WW + px;
    const int warpPos = ly*14 + lx;

    if (tid < 140) {
        int hy = tid / 14, hx = tid - hy*14;
        int gy = min(max((int)blockIdx.y*4 + hy - 3, 0), HH-1);
        int gx = min(max((int)blockIdx.x*8 + hx - 3, 0), WW-1);
        sgp[tid] = (gy*WW + gx)*HCH;
    }
    __syncthreads();

    // ---- stage all 4 frames of g halos, bf16 channel-major [t][h][141] ----
    const __nv_bfloat16* gBase = g_gb + (size_t)b*TC*HW*HCH;
    for (int i = tid; i < 560*32; i += 1024) {
        int h2  = i & 31;          // channel pair 2h2, 2h2+1
        int pr  = i >> 5;
        int pos = pr % 140;
        int t   = pr / 140;
        unsigned int v = *(const unsigned int*)(gBase + (size_t)t*HW*HCH + sgp[pos] + 2*h2);
        __nv_bfloat162 bv = *(__nv_bfloat162*)&v;
        sgm16[(t*64 + 2*h2    )*141 + pos] = bv.x;
        sgm16[(t*64 + 2*h2 + 1)*141 + pos] = bv.y;
    }

    // ---- q for this pixel ----
    const float* qb = g_q + ((size_t)b*HW + p)*HCH;
    const int c   = lane & 7;    // channel chunk within key group
    const int sub = lane >> 3;   // key within group of 4
    float4 qv0 = *(const float4*)(qb + c*4);
    float4 qv1 = *(const float4*)(qb + c*4 + 32);
    float  q0r = qb[lane], q1r = qb[lane + 32];

    // ---- pass 1: scores (phi fp32, unscrambled) ----
    const float* pBase = g_phi + (size_t)b*TC*HW*HCH;
    for (int t = 0; t < TC; t++) {
        __syncthreads();
        for (int i = tid; i < 140*16; i += 1024) {
            int c4 = i & 15, pos = i >> 4;
            *(float4*)(sphi + pos*68 + c4*4) =
                *(const float4*)(pBase + (size_t)t*HW*HCH + sgp[pos] + c4*4);
        }
        __syncthreads();

        #pragma unroll
        for (int g2 = 0; g2 < 12; g2++) {
            int q  = g2*4 + sub;
            int dy = q / 7, dx = q - dy*7;
            int pos = warpPos + dy*14 + dx;
            const float4* pr4 = (const float4*)(sphi + pos*68);
            float4 p0 = pr4[c];
            float4 p1 = pr4[8 + c];
            float s = qv0.x*p0.x + qv0.y*p0.y + qv0.z*p0.z + qv0.w*p0.w
                    + qv1.x*p1.x + qv1.y*p1.y + qv1.z*p1.z + qv1.w*p1.w;
            s += __shfl_xor_sync(0xffffffffu, s, 4);
            s += __shfl_xor_sync(0xffffffffu, s, 2);
            s += __shfl_xor_sync(0xffffffffu, s, 1);
            if (c == 0) satt[warp*200 + t*49 + q] = s * 8.0f;
        }
        {   // leftover key q=48
            int pos = warpPos + 90;
            float s = q0r*sphi[pos*68 + lane] + q1r*sphi[pos*68 + lane + 32];
            s += __shfl_xor_sync(0xffffffffu, s, 16);
            s += __shfl_xor_sync(0xffffffffu, s, 8);
            s += __shfl_xor_sync(0xffffffffu, s, 4);
            s += __shfl_xor_sync(0xffffffffu, s, 2);
            s += __shfl_xor_sync(0xffffffffu, s, 1);
            if (lane == 0) satt[warp*200 + t*49 + 48] = s * 8.0f;
        }
    }
    __syncthreads();   // pass-1 phi reads done; union region free

    // ---- compute scramble table (ushort) into union region ----
    {
        unsigned short* dst = (unsigned short*)(smc + UNI_B);
        for (int i = tid; i < 12544; i += 1024) {
            int h  = i / 196;
            int r  = i - h*196;
            int t  = r / 49;
            int q  = r - t*49;
            int dy = q / 7;
            int dx = q - dy*7;
            dst[i] = (unsigned short)((t*64 + h)*141 + dy*14 + dx);
        }
    }

    // ---- per-warp softmax (deferred normalization) ----
    float sv[7];
    float m = -1e30f;
    #pragma unroll
    for (int g2 = 0; g2 < 7; g2++) {
        int k = lane + 32*g2;
        sv[g2] = (k < 196) ? satt[warp*200 + k] : -1e30f;
        m = fmaxf(m, sv[g2]);
    }
    m = fmaxf(m, __shfl_xor_sync(0xffffffffu, m, 16));
    m = fmaxf(m, __shfl_xor_sync(0xffffffffu, m, 8));
    m = fmaxf(m, __shfl_xor_sync(0xffffffffu, m, 4));
    m = fmaxf(m, __shfl_xor_sync(0xffffffffu, m, 2));
    m = fmaxf(m, __shfl_xor_sync(0xffffffffu, m, 1));
    float tot = 0.f;
    #pragma unroll
    for (int g2 = 0; g2 < 7; g2++) {
        int k = lane + 32*g2;
        if (k < 196) {
            float e = __expf(sv[g2] - m);
            satt[warp*200 + k] = e;
            tot += e;
        }
    }
    tot += __shfl_xor_sync(0xffffffffu, tot, 16);
    tot += __shfl_xor_sync(0xffffffffu, tot, 8);
    tot += __shfl_xor_sync(0xffffffffu, tot, 4);
    tot += __shfl_xor_sync(0xffffffffu, tot, 2);
    tot += __shfl_xor_sync(0xffffffffu, tot, 1);
    float inv = 1.0f / tot;

    __syncthreads();   // offT ready

    // ---- pass 2: scrambled-V accumulation (channels 2*lane, 2*lane+1) ----
    const ushort2* soff2 = (const ushort2*)(smc + UNI_B);
    float acc0 = 0.f, acc1 = 0.f;
    for (int k = 0; k < 196; k += 4) {
        float4 w4 = *(const float4*)(satt + warp*200 + k);
        float wv[4] = {w4.x, w4.y, w4.z, w4.w};
        #pragma unroll
        for (int u = 0; u < 4; u++) {
            ushort2 o = soff2[(k + u)*32 + lane];
            acc0 = fmaf(wv[u], __bfloat162float(sgm16[o.x + warpPos]), acc0);
            acc1 = fmaf(wv[u], __bfloat162float(sgm16[o.y + warpPos]), acc1);
        }
    }
    float* yb = g_y + ((size_t)b*HW + p)*HCH;
    *(float2*)(yb + 2*lane) = make_float2(acc0*inv, acc1*inv);
}

// ---------------------------------------------------------------------------
// Kernel 3: output projection + residual (handles the y-reshape scramble).
// out[b,c,s] = x[b,c,0,s] + sum_h' w_out[c,h'] * y_flat[b][h'*2304 + s]
// grid (36,2,2), block 512, microtile 2c x 4s.
// ---------------------------------------------------------------------------
__global__ void out_kernel(const float* __restrict__ x,
                           const float* __restrict__ w_out,
                           float* __restrict__ out)
{
    __shared__ float sy [64*64];   // [h'][s]
    __shared__ float swt[64*68];   // [h'][c]
    const int s0  = blockIdx.x * 64;
    const int c0  = blockIdx.y * 64;
    const int b   = blockIdx.z;
    const int tid = threadIdx.x;
    const float* yb = g_y + (size_t)b*HW*HCH;
    for (int i = tid; i < 4096; i += 512) {
        int hh = i >> 6, s = i & 63;
        sy[i] = yb[hh*HW + s0 + s];
        int cc = i >> 6, h2 = i & 63;
        swt[h2*68 + cc] = w_out[(c0 + cc)*HCH + h2];
    }
    __syncthreads();
    const int sg2 = tid & 15;   // s = sg2*4 + i
    const int cg  = tid >> 4;   // c = cg*2 + j
    float acc[2][4] = {};
    #pragma unroll 4
    for (int hh = 0; hh < 64; hh++) {
        float4 yv = *(const float4*)(sy + hh*64 + sg2*4);
        float2 wv = *(const float2*)(swt + hh*68 + cg*2);
        float ys[4] = {yv.x, yv.y, yv.z, yv.w};
        float ws[2] = {wv.x, wv.y};
        #pragma unroll
        for (int j = 0; j < 2; j++)
            #pragma unroll
            for (int i = 0; i < 4; i++)
                acc[j][i] = fmaf(ws[j], ys[i], acc[j][i]);
    }
    #pragma unroll
    for (int j = 0; j < 2; j++) {
        int cc = c0 + cg*2 + j;
        float4 xv = *(const float4*)(x + ((size_t)(b*CIN + cc)*TT)*HW + s0 + sg2*4);
        float4 o  = make_float4(acc[j][0]+xv.x, acc[j][1]+xv.y,
                                acc[j][2]+xv.z, acc[j][3]+xv.w);
        *(float4*)(out + ((size_t)(b*CIN + cc))*HW + s0 + sg2*4) = o;
    }
}

extern "C" void kernel_launch(void* const* d_in, const int* in_sizes, int n_in,
                              void* d_out, int out_size)
{
    const float* x  = (const float*)d_in[0];
    const float* wt = (const float*)d_in[1];
    const float* wp = (const float*)d_in[2];
    const float* wg = (const float*)d_in[3];
    const float* wo = (const float*)d_in[4];
    float* out = (float*)d_out;

    cudaFuncSetAttribute(proj_kernel, cudaFuncAttributeMaxDynamicSharedMemorySize, PROJ_SMEM);
    cudaFuncSetAttribute(attn_kernel, cudaFuncAttributeMaxDynamicSharedMemorySize, SMEM_B);

    proj_kernel<<<dim3(36, 5, 2), 256, PROJ_SMEM>>>(x, wt, wp, wg);
    attn_kernel<<<dim3(6, 12, 2), 1024, SMEM_B>>>();
    out_kernel<<<dim3(36, 2, 2), 512>>>(x, wo, out);
}